// round 2
// baseline (speedup 1.0000x reference)
#include <cuda_runtime.h>
#include <cuda.h>
#include <cuda_bf16.h>
#include <cstdint>

// ============================================================================
// Problem constants
// ============================================================================
#define K_DIM   1024
#define M_OUT   1024
#define N_MAX   32768

#define TM      128      // CTA tile rows (x rows)
#define TN      128      // CTA tile cols (weight rows)
#define KC      64       // K elems per pipeline chunk (64 bf16 = 128B row, SW128)
#define STAGES  4
#define KITERS  (K_DIM / KC)   // 16
#define NTHREADS 288           // 9 warps

// SMEM layout (dynamic)
#define SM_TMEM  0
#define SM_MBAR  16                    // ring: full at 16+16s, empty at 24+16s
#define SM_DONE  (16 + 16 * STAGES)
#define SM_BIAS  128                   // 128 floats
#define SM_A     1024
#define SM_B     (1024 + STAGES * 16384)
#define STAGE_BYTES 16384
#define SMEM_TOTAL (1024 + 2 * STAGES * 16384)   // 132096

// tcgen05 available only on arch-'a' device passes (or host pass for parsing)
#if !defined(__CUDA_ARCH__) || defined(__CUDA_ARCH_FEAT_SM103_ALL) || defined(__CUDA_ARCH_FEAT_SM100_ALL)
#define TCGEN05_OK 1
#endif

// idesc: kind::f16, dtype=F32(1<<4), atype=BF16(1<<7), btype=BF16(1<<10),
// N>>3 at bit17, M>>4 at bit24
#define MMA_IDESC ((1u << 4) | (1u << 7) | (1u << 10) | ((TN / 8) << 17) | ((TM / 16) << 24))

// ============================================================================
// Scratch (__device__ globals; no allocation allowed)
// ============================================================================
__device__ __nv_bfloat16 g_qx[(size_t)N_MAX * K_DIM];   // 64 MB
__device__ __nv_bfloat16 g_qw[(size_t)M_OUT * K_DIM];   //  2 MB
__device__ unsigned g_absmax[2];

// ============================================================================
// Base-target PTX helpers (sm_90-era; fine on sm_103 base)
// ============================================================================
__device__ __forceinline__ uint32_t smem_u32(const void* p) {
    return (uint32_t)__cvta_generic_to_shared(p);
}
__device__ __forceinline__ uint32_t elect1() {
    uint32_t pred;
    asm volatile("{\n\t.reg .pred p;\n\telect.sync _|p, 0xFFFFFFFF;\n\t"
                 "selp.b32 %0, 1, 0, p;\n\t}" : "=r"(pred));
    return pred;
}
__device__ __forceinline__ void mbar_init(uint32_t mbar, uint32_t count) {
    asm volatile("mbarrier.init.shared.b64 [%0], %1;" :: "r"(mbar), "r"(count) : "memory");
}
__device__ __forceinline__ void mbar_expect_tx(uint32_t mbar, uint32_t bytes) {
    asm volatile("mbarrier.arrive.expect_tx.shared.b64 _, [%0], %1;"
                 :: "r"(mbar), "r"(bytes) : "memory");
}
__device__ __forceinline__ void mbar_arrive(uint32_t mbar) {
    asm volatile("mbarrier.arrive.shared.b64 _, [%0];" :: "r"(mbar) : "memory");
}
__device__ __forceinline__ void mbar_wait(uint32_t mbar, uint32_t parity) {
    uint32_t done;
    asm volatile("{\n\t.reg .pred p;\n\t"
                 "mbarrier.try_wait.parity.acquire.cta.shared::cta.b64 p, [%1], %2;\n\t"
                 "selp.b32 %0, 1, 0, p;\n\t}"
                 : "=r"(done) : "r"(mbar), "r"(parity) : "memory");
    while (!done) {
        asm volatile("{\n\t.reg .pred p;\n\t"
                     "mbarrier.try_wait.parity.acquire.cta.shared::cta.b64 p, [%1], %2, 0x989680;\n\t"
                     "selp.b32 %0, 1, 0, p;\n\t}"
                     : "=r"(done) : "r"(mbar), "r"(parity) : "memory");
    }
}
__device__ __forceinline__ void tma2d(uint32_t dst, const CUtensorMap* tm,
                                      int cx, int cy, uint32_t mbar) {
    asm volatile("cp.async.bulk.tensor.2d.shared::cta.global.tile.mbarrier::complete_tx::bytes "
                 "[%0], [%1, {%2, %3}], [%4];"
                 :: "r"(dst), "l"(tm), "r"(cx), "r"(cy), "r"(mbar) : "memory");
}
// ldmatrix 4x 8x8 b16 (non-trans)
__device__ __forceinline__ void ldsm4(uint32_t* r, uint32_t addr) {
    asm volatile("ldmatrix.sync.aligned.m8n8.x4.shared.b16 {%0,%1,%2,%3}, [%4];"
                 : "=r"(r[0]), "=r"(r[1]), "=r"(r[2]), "=r"(r[3]) : "r"(addr));
}
// legacy HMMA m16n8k16 bf16 -> f32
__device__ __forceinline__ void mma16816(float* c, const uint32_t* a, const uint32_t* b) {
    asm volatile("mma.sync.aligned.m16n8k16.row.col.f32.bf16.bf16.f32 "
                 "{%0,%1,%2,%3}, {%4,%5,%6,%7}, {%8,%9}, {%0,%1,%2,%3};"
                 : "+f"(c[0]), "+f"(c[1]), "+f"(c[2]), "+f"(c[3])
                 : "r"(a[0]), "r"(a[1]), "r"(a[2]), "r"(a[3]), "r"(b[0]), "r"(b[1]));
}

// ============================================================================
// tcgen05 helpers — only compiled on 'a' targets
// ============================================================================
#ifdef TCGEN05_OK
__device__ __forceinline__ void tmem_alloc(uint32_t smem_dst, uint32_t ncols) {
    asm volatile("tcgen05.alloc.cta_group::1.sync.aligned.shared::cta.b32 [%0], %1;"
                 :: "r"(smem_dst), "r"(ncols) : "memory");
}
__device__ __forceinline__ void tmem_dealloc(uint32_t tmem, uint32_t ncols) {
    asm volatile("tcgen05.dealloc.cta_group::1.sync.aligned.b32 %0, %1;" :: "r"(tmem), "r"(ncols));
}
__device__ __forceinline__ void tmem_relinquish() {
    asm volatile("tcgen05.relinquish_alloc_permit.cta_group::1.sync.aligned;");
}
__device__ __forceinline__ void tc_commit(uint32_t mbar) {
    asm volatile("tcgen05.commit.cta_group::1.mbarrier::arrive::one.shared::cluster.b64 [%0];"
                 :: "r"(mbar) : "memory");
}
__device__ __forceinline__ void tc_fence_before() {
    asm volatile("tcgen05.fence::before_thread_sync;" ::: "memory");
}
__device__ __forceinline__ void tc_fence_after() {
    asm volatile("tcgen05.fence::after_thread_sync;" ::: "memory");
}
__device__ __forceinline__ void tc_wait_ld() {
    asm volatile("tcgen05.wait::ld.sync.aligned;" ::: "memory");
}
__device__ __forceinline__ void mma_f16_ss(uint32_t d_tmem, uint64_t a_desc, uint64_t b_desc,
                                           uint32_t idesc, uint32_t enable) {
    asm volatile("{\n\t.reg .pred p;\n\tsetp.ne.u32 p, %5, 0;\n\t"
                 "tcgen05.mma.cta_group::1.kind::f16 [%0], %1, %2, %3, {%4, %4, %4, %4}, p;\n\t}"
                 :: "r"(d_tmem), "l"(a_desc), "l"(b_desc), "r"(idesc), "r"(0u), "r"(enable)
                 : "memory");
}
__device__ __forceinline__ void tmem_ld32(uint32_t* r, uint32_t addr) {
    asm volatile(
        "tcgen05.ld.sync.aligned.32x32b.x32.b32 "
        "{%0, %1, %2, %3, %4, %5, %6, %7, "
        " %8, %9, %10, %11, %12, %13, %14, %15, "
        " %16, %17, %18, %19, %20, %21, %22, %23, "
        " %24, %25, %26, %27, %28, %29, %30, %31}, [%32];"
        : "=r"(r[0]),  "=r"(r[1]),  "=r"(r[2]),  "=r"(r[3]),
          "=r"(r[4]),  "=r"(r[5]),  "=r"(r[6]),  "=r"(r[7]),
          "=r"(r[8]),  "=r"(r[9]),  "=r"(r[10]), "=r"(r[11]),
          "=r"(r[12]), "=r"(r[13]), "=r"(r[14]), "=r"(r[15]),
          "=r"(r[16]), "=r"(r[17]), "=r"(r[18]), "=r"(r[19]),
          "=r"(r[20]), "=r"(r[21]), "=r"(r[22]), "=r"(r[23]),
          "=r"(r[24]), "=r"(r[25]), "=r"(r[26]), "=r"(r[27]),
          "=r"(r[28]), "=r"(r[29]), "=r"(r[30]), "=r"(r[31])
        : "r"(addr));
}
static constexpr uint64_t SMEM_DESC_BASE_SW128 =
    (uint64_t(2) << 61) | (uint64_t(1) << 46) | (uint64_t(64) << 32) | (uint64_t(1) << 16);
__device__ __forceinline__ uint64_t make_desc(uint32_t smem_addr) {
    return SMEM_DESC_BASE_SW128 | ((uint64_t)(smem_addr >> 4) & 0x3FFF);
}
#endif // TCGEN05_OK

// ============================================================================
// Kernel 1: per-tensor absmax
// ============================================================================
__global__ void absmax_kernel(const float4* __restrict__ in, int n4, unsigned* __restrict__ out) {
    float m = 0.0f;
    for (int i = blockIdx.x * blockDim.x + threadIdx.x; i < n4; i += gridDim.x * blockDim.x) {
        float4 v = in[i];
        m = fmaxf(m, fabsf(v.x)); m = fmaxf(m, fabsf(v.y));
        m = fmaxf(m, fabsf(v.z)); m = fmaxf(m, fabsf(v.w));
    }
#pragma unroll
    for (int o = 16; o > 0; o >>= 1)
        m = fmaxf(m, __shfl_xor_sync(0xFFFFFFFFu, m, o));
    if ((threadIdx.x & 31) == 0) atomicMax(out, __float_as_uint(m));
}

// ============================================================================
// Kernel 2: quantize to int8 codes stored as bf16 (exact for |q| <= 127)
// Matches reference exactly: scale = max/127 (f32), q = rint(t/scale) IEEE div.
// ============================================================================
__global__ void quant_kernel(const float4* __restrict__ in, uint2* __restrict__ outq,
                             int n4, const unsigned* __restrict__ absmax_bits) {
    float s = __uint_as_float(*absmax_bits) * (1.0f / 127.0f);
    // NOTE: max/127 must be IEEE: compute via division, not reciprocal
    s = __uint_as_float(*absmax_bits) / 127.0f;
    for (int i = blockIdx.x * blockDim.x + threadIdx.x; i < n4; i += gridDim.x * blockDim.x) {
        float4 v = in[i];
        float q0 = fminf(fmaxf(rintf(v.x / s), -127.0f), 127.0f);
        float q1 = fminf(fmaxf(rintf(v.y / s), -127.0f), 127.0f);
        float q2 = fminf(fmaxf(rintf(v.z / s), -127.0f), 127.0f);
        float q3 = fminf(fmaxf(rintf(v.w / s), -127.0f), 127.0f);
        __nv_bfloat162 p01 = __floats2bfloat162_rn(q0, q1);
        __nv_bfloat162 p23 = __floats2bfloat162_rn(q2, q3);
        uint2 o;
        o.x = *reinterpret_cast<uint32_t*>(&p01);
        o.y = *reinterpret_cast<uint32_t*>(&p23);
        outq[i] = o;
    }
}

// ============================================================================
// Kernel 3: GEMM  out[m][n] = acc(m,n) * (sx*sw) + bias[n]
//   9 warps. Warp 8 = TMA producer (both paths).
//   tcgen05 path: warp 8 also issues nothing else; warp 7 = MMA issuer,
//                 warps 0-3 = TMEM epilogue readers.
//   fallback path: warps 0-7 = HMMA compute (each 32m x 64n), warp 8 producer.
// ============================================================================
__global__ void __launch_bounds__(NTHREADS, 1) gemm_kernel(
    const __grid_constant__ CUtensorMap tmA,
    const __grid_constant__ CUtensorMap tmB,
    const float* __restrict__ bias,
    float* __restrict__ out,
    const unsigned* __restrict__ absmax_bits)
{
    extern __shared__ __align__(1024) char smem[];
    uint32_t sb = smem_u32(smem);
    const int tid = threadIdx.x;
    const int wid = tid >> 5;
    const int lid = tid & 31;
    const int n_base = blockIdx.x * TN;
    const int m_base = blockIdx.y * TM;

    if (tid < TN)
        reinterpret_cast<float*>(smem + SM_BIAS)[tid] = bias[n_base + tid];

#if defined(__CUDA_ARCH__) && defined(TCGEN05_OK)
    // ------------------------------------------------------------------
    // tcgen05 path (sm_103a cubin)
    // ------------------------------------------------------------------
    if (tid == 0) {
        for (int s = 0; s < STAGES; s++) {
            mbar_init(sb + SM_MBAR + 16 * s, 1);       // full
            mbar_init(sb + SM_MBAR + 16 * s + 8, 1);   // empty (MMA commit arrives)
        }
        mbar_init(sb + SM_DONE, 1);
        asm volatile("fence.proxy.async.shared::cta;" ::: "memory");
    }
    if (wid == 7)
        tmem_alloc(sb + SM_TMEM, 128);
    __syncthreads();

    uint32_t tmem_base;
    asm volatile("ld.shared.b32 %0, [%1];" : "=r"(tmem_base) : "r"(sb + SM_TMEM));

    if (wid == 8) {                       // TMA producer
        if (elect1()) {
            int s = 0, ph = 1;
            for (int kc = 0; kc < KITERS; kc++) {
                mbar_wait(sb + SM_MBAR + 16 * s + 8, ph);
                mbar_expect_tx(sb + SM_MBAR + 16 * s, 2 * STAGE_BYTES);
                tma2d(sb + SM_A + s * STAGE_BYTES, &tmA, kc * KC, m_base, sb + SM_MBAR + 16 * s);
                tma2d(sb + SM_B + s * STAGE_BYTES, &tmB, kc * KC, n_base, sb + SM_MBAR + 16 * s);
                if (++s == STAGES) { s = 0; ph ^= 1; }
            }
        }
    } else if (wid == 7) {                // MMA issuer
        if (elect1()) {
            int s = 0, ph = 0;
            for (int kc = 0; kc < KITERS; kc++) {
                mbar_wait(sb + SM_MBAR + 16 * s, ph);
                uint64_t ad = make_desc(sb + SM_A + s * STAGE_BYTES);
                uint64_t bd = make_desc(sb + SM_B + s * STAGE_BYTES);
#pragma unroll
                for (int ks = 0; ks < 4; ks++)
                    mma_f16_ss(tmem_base, ad + ks * 2, bd + ks * 2, MMA_IDESC,
                               (kc == 0 && ks == 0) ? 0u : 1u);
                tc_commit(sb + SM_MBAR + 16 * s + 8);
                if (++s == STAGES) { s = 0; ph ^= 1; }
            }
            tc_commit(sb + SM_DONE);
        }
    } else if (wid < 4) {                 // epilogue warps
        float scale = (__uint_as_float(absmax_bits[0]) / 127.0f) *
                      (__uint_as_float(absmax_bits[1]) / 127.0f);
        mbar_wait(sb + SM_DONE, 0);
        tc_fence_after();

        int m = m_base + wid * 32 + lid;
        float* orow = out + (size_t)m * M_OUT + n_base;
        const float* bsm = reinterpret_cast<const float*>(smem + SM_BIAS);
        for (int c0 = 0; c0 < TN; c0 += 32) {
            uint32_t r[32];
            tmem_ld32(r, tmem_base + c0);
            tc_wait_ld();
#pragma unroll
            for (int j = 0; j < 32; j += 4) {
                float4 v;
                v.x = __uint_as_float(r[j + 0]) * scale + bsm[c0 + j + 0];
                v.y = __uint_as_float(r[j + 1]) * scale + bsm[c0 + j + 1];
                v.z = __uint_as_float(r[j + 2]) * scale + bsm[c0 + j + 2];
                v.w = __uint_as_float(r[j + 3]) * scale + bsm[c0 + j + 3];
                *reinterpret_cast<float4*>(orow + c0 + j) = v;
            }
        }
        tc_fence_before();
    }

    __syncthreads();
    if (wid == 7) {
        tmem_relinquish();
        tmem_dealloc(tmem_base, 128);
    }
#else
    // ------------------------------------------------------------------
    // Fallback path (base sm_103 cubin): legacy HMMA mma.sync
    // ------------------------------------------------------------------
    if (tid == 0) {
        for (int s = 0; s < STAGES; s++) {
            mbar_init(sb + SM_MBAR + 16 * s, 1);       // full (producer expect_tx)
            mbar_init(sb + SM_MBAR + 16 * s + 8, 8);   // empty (8 compute warps arrive)
        }
        asm volatile("fence.proxy.async.shared::cta;" ::: "memory");
    }
    __syncthreads();

    if (wid == 8) {                       // TMA producer
        if (elect1()) {
            int s = 0, ph = 1;
            for (int kc = 0; kc < KITERS; kc++) {
                mbar_wait(sb + SM_MBAR + 16 * s + 8, ph);
                mbar_expect_tx(sb + SM_MBAR + 16 * s, 2 * STAGE_BYTES);
                tma2d(sb + SM_A + s * STAGE_BYTES, &tmA, kc * KC, m_base, sb + SM_MBAR + 16 * s);
                tma2d(sb + SM_B + s * STAGE_BYTES, &tmB, kc * KC, n_base, sb + SM_MBAR + 16 * s);
                if (++s == STAGES) { s = 0; ph ^= 1; }
            }
        }
    } else {                              // 8 compute warps
        const int m0 = (wid >> 1) * 32;   // warp m offset within CTA tile
        const int n0 = (wid & 1) * 64;    // warp n offset within CTA tile

        // ldmatrix lane address components (SW128 swizzle on 128B rows:
        // swz(r*128 + c) = r*128 + (c ^ ((r&7)<<4)) since c < 128)
        const int arow_l = lid & 15;            // A: lanes 0-15 rows, 16-31 k+8 half
        const int acol_l = (lid >> 4) * 16;     // +16B for k8-15 matrices
        const int xo_a   = (arow_l & 7) << 4;
        const int brow_l = (lid & 7) + ((lid >> 4) << 3);  // B: n row within 16
        const int bcol_l = ((lid >> 3) & 1) * 16;
        const int xo_b   = (brow_l & 7) << 4;

        float acc[2][8][4];
#pragma unroll
        for (int mt = 0; mt < 2; mt++)
#pragma unroll
            for (int nt = 0; nt < 8; nt++)
#pragma unroll
                for (int j = 0; j < 4; j++) acc[mt][nt][j] = 0.0f;

        int s = 0, ph = 0;
        for (int kc = 0; kc < KITERS; kc++) {
            mbar_wait(sb + SM_MBAR + 16 * s, ph);
            uint32_t baseA = sb + SM_A + s * STAGE_BYTES;
            uint32_t baseB = sb + SM_B + s * STAGE_BYTES;
#pragma unroll
            for (int kk = 0; kk < 4; kk++) {
                uint32_t af[2][4];
#pragma unroll
                for (int mt = 0; mt < 2; mt++) {
                    int r = m0 + mt * 16 + arow_l;
                    ldsm4(af[mt], baseA + r * 128 + ((kk * 32 + acol_l) ^ xo_a));
                }
                uint32_t bf[8][2];
#pragma unroll
                for (int np = 0; np < 4; np++) {
                    int r = n0 + np * 16 + brow_l;
                    uint32_t t4[4];
                    ldsm4(t4, baseB + r * 128 + ((kk * 32 + bcol_l) ^ xo_b));
                    bf[2 * np][0] = t4[0]; bf[2 * np][1] = t4[1];
                    bf[2 * np + 1][0] = t4[2]; bf[2 * np + 1][1] = t4[3];
                }
#pragma unroll
                for (int mt = 0; mt < 2; mt++)
#pragma unroll
                    for (int nt = 0; nt < 8; nt++)
                        mma16816(acc[mt][nt], af[mt], bf[nt]);
            }
            if (lid == 0) mbar_arrive(sb + SM_MBAR + 16 * s + 8);
            if (++s == STAGES) { s = 0; ph ^= 1; }
        }

        // Epilogue: scale + bias, direct stores
        float scale = (__uint_as_float(absmax_bits[0]) / 127.0f) *
                      (__uint_as_float(absmax_bits[1]) / 127.0f);
        const float* bsm = reinterpret_cast<const float*>(smem + SM_BIAS);
        const int r4 = lid >> 2;
        const int c2 = (lid & 3) * 2;
#pragma unroll
        for (int mt = 0; mt < 2; mt++) {
#pragma unroll
            for (int nt = 0; nt < 8; nt++) {
                int cn = n0 + nt * 8 + c2;
                float b0 = bsm[cn], b1 = bsm[cn + 1];
                int gm = m_base + m0 + mt * 16 + r4;
                float2 v0, v1;
                v0.x = acc[mt][nt][0] * scale + b0;
                v0.y = acc[mt][nt][1] * scale + b1;
                v1.x = acc[mt][nt][2] * scale + b0;
                v1.y = acc[mt][nt][3] * scale + b1;
                *reinterpret_cast<float2*>(out + (size_t)gm * M_OUT + n_base + cn) = v0;
                *reinterpret_cast<float2*>(out + (size_t)(gm + 8) * M_OUT + n_base + cn) = v1;
            }
        }
    }
#endif
}

// ============================================================================
// Host launch
// ============================================================================
typedef CUresult (*tmap_encode_fn)(
    CUtensorMap*, CUtensorMapDataType, cuuint32_t, void*,
    const cuuint64_t*, const cuuint64_t*, const cuuint32_t*, const cuuint32_t*,
    CUtensorMapInterleave, CUtensorMapSwizzle, CUtensorMapL2promotion, CUtensorMapFloatOOBfill);

extern "C" void kernel_launch(void* const* d_in, const int* in_sizes, int n_in,
                              void* d_out, int out_size) {
    const float* x    = (const float*)d_in[0];
    const float* w    = (const float*)d_in[1];
    const float* bias = (const float*)d_in[2];
    float* out = (float*)d_out;

    int n_rows = in_sizes[0] / K_DIM;   // 32768
    int n4x = in_sizes[0] / 4;
    int n4w = in_sizes[1] / 4;

    void *qx_ptr, *qw_ptr, *am_ptr;
    cudaGetSymbolAddress(&qx_ptr, g_qx);
    cudaGetSymbolAddress(&qw_ptr, g_qw);
    cudaGetSymbolAddress(&am_ptr, g_absmax);
    unsigned* am = (unsigned*)am_ptr;

    cudaMemsetAsync(am_ptr, 0, 2 * sizeof(unsigned));

    absmax_kernel<<<2048, 256>>>((const float4*)x, n4x, am);
    absmax_kernel<<<256, 256>>>((const float4*)w, n4w, am + 1);
    quant_kernel<<<2048, 256>>>((const float4*)x, (uint2*)qx_ptr, n4x, am);
    quant_kernel<<<256, 256>>>((const float4*)w, (uint2*)qw_ptr, n4w, am + 1);

    void* fp = nullptr;
    cudaDriverEntryPointQueryResult qr;
#if CUDART_VERSION >= 12050
    cudaGetDriverEntryPointByVersion("cuTensorMapEncodeTiled", &fp, 12000,
                                     cudaEnableDefault, &qr);
#else
    cudaGetDriverEntryPoint("cuTensorMapEncodeTiled", &fp, cudaEnableDefault, &qr);
#endif
    tmap_encode_fn encode = (tmap_encode_fn)fp;

    CUtensorMap tmA, tmB;
    {
        cuuint64_t dims[2]   = {K_DIM, (cuuint64_t)n_rows};
        cuuint64_t stride[1] = {K_DIM * sizeof(__nv_bfloat16)};
        cuuint32_t box[2]    = {KC, TM};
        cuuint32_t es[2]     = {1, 1};
        encode(&tmA, CU_TENSOR_MAP_DATA_TYPE_BFLOAT16, 2, qx_ptr, dims, stride, box, es,
               CU_TENSOR_MAP_INTERLEAVE_NONE, CU_TENSOR_MAP_SWIZZLE_128B,
               CU_TENSOR_MAP_L2_PROMOTION_L2_128B, CU_TENSOR_MAP_FLOAT_OOB_FILL_NONE);
    }
    {
        cuuint64_t dims[2]   = {K_DIM, M_OUT};
        cuuint64_t stride[1] = {K_DIM * sizeof(__nv_bfloat16)};
        cuuint32_t box[2]    = {KC, TN};
        cuuint32_t es[2]     = {1, 1};
        encode(&tmB, CU_TENSOR_MAP_DATA_TYPE_BFLOAT16, 2, qw_ptr, dims, stride, box, es,
               CU_TENSOR_MAP_INTERLEAVE_NONE, CU_TENSOR_MAP_SWIZZLE_128B,
               CU_TENSOR_MAP_L2_PROMOTION_L2_128B, CU_TENSOR_MAP_FLOAT_OOB_FILL_NONE);
    }

    cudaFuncSetAttribute(gemm_kernel, cudaFuncAttributeMaxDynamicSharedMemorySize, SMEM_TOTAL);
    gemm_kernel<<<dim3(M_OUT / TN, n_rows / TM), NTHREADS, SMEM_TOTAL>>>(tmA, tmB, bias, out, am);
}